// round 7
// baseline (speedup 1.0000x reference)
#include <cuda_runtime.h>
#include <cstdint>

#define SEQ 2048
#define DIM 128
#define BHN 32
#define NROWS (BHN * SEQ)   // 65536 rows each for q and k

// Scratch: reciprocal L2 norms (no device allocation allowed -> __device__ globals)
__device__ float g_rq[NROWS];
__device__ float g_rk[NROWS];

// ---------------------------------------------------------------------------
// Kernel 1: per-row 1/max(||x||, 1e-12). One warp per row.
// ---------------------------------------------------------------------------
__global__ void norm_kernel(const float* __restrict__ q, const float* __restrict__ k) {
    int gwarp = (blockIdx.x * blockDim.x + threadIdx.x) >> 5;
    int lane = threadIdx.x & 31;
    bool is_q = gwarp < NROWS;
    int row = is_q ? gwarp : gwarp - NROWS;
    const float* src = is_q ? q : k;
    float4 v = reinterpret_cast<const float4*>(src + (size_t)row * DIM)[lane];
    float ss = v.x * v.x + v.y * v.y + v.z * v.z + v.w * v.w;
#pragma unroll
    for (int o = 16; o > 0; o >>= 1) ss += __shfl_xor_sync(0xffffffffu, ss, o);
    if (lane == 0) {
        float r = 1.0f / fmaxf(sqrtf(ss), 1e-12f);
        if (is_q) g_rq[row] = r; else g_rk[row] = r;
    }
}

// ---------------------------------------------------------------------------
// Helpers
// ---------------------------------------------------------------------------
__device__ __forceinline__ uint32_t smem_to_u32(const void* p) {
    uint32_t a;
    asm("{ .reg .u64 t; cvta.to.shared.u64 t, %1; cvt.u32.u64 %0, t; }" : "=r"(a) : "l"(p));
    return a;
}

#define CP_ASYNC16(dst, src) \
    asm volatile("cp.async.ca.shared.global [%0], [%1], 16;" :: "r"(dst), "l"(src))
#define CP_COMMIT() asm volatile("cp.async.commit_group;" ::: "memory")
#define CP_WAIT(n)  asm volatile("cp.async.wait_group %0;" :: "n"(n) : "memory")

__device__ __forceinline__ void ldsm_x4(unsigned r[4], uint32_t addr) {
    asm volatile("ldmatrix.sync.aligned.m8n8.x4.shared.b16 {%0,%1,%2,%3}, [%4];"
                 : "=r"(r[0]), "=r"(r[1]), "=r"(r[2]), "=r"(r[3]) : "r"(addr));
}

__device__ __forceinline__ void mma_tf32(float c[4], const unsigned a[4],
                                         unsigned b0, unsigned b1) {
    asm volatile(
        "mma.sync.aligned.m16n8k8.row.col.f32.tf32.tf32.f32 "
        "{%0,%1,%2,%3}, {%4,%5,%6,%7}, {%8,%9}, {%0,%1,%2,%3};\n"
        : "+f"(c[0]), "+f"(c[1]), "+f"(c[2]), "+f"(c[3])
        : "r"(a[0]), "r"(a[1]), "r"(a[2]), "r"(a[3]), "r"(b0), "r"(b1));
}

__device__ __forceinline__ float ex2f(float x) {
    float y;
    asm("ex2.approx.f32 %0, %1;" : "=f"(y) : "f"(x));
    return y;
}

// ---------------------------------------------------------------------------
// Kernel 2: fat-warp-tile GEMM + exp epilogue. 1 CTA/SM, 256 threads.
// CTA tile: M=128 (q rows, resident A) x N=256 (k rows) x K=128.
// CTA loops over 4 bn-tiles (persistent). B double-buffered in K-chunks
// of 32 (issue distance 2), so next-tile loads overlap epilogue.
// Warp grid 2x4, warp tile 64x64 (acc 128 regs/lane).
// smem: A[128][132] fp32 @0 (67584 B), B stages 2 x [256][36] fp32 (36864 B).
// Total 141312 B.
// ---------------------------------------------------------------------------
#define LDA 132
#define LDB 36
#define SM_B0 67584
#define B_STAGE (256 * LDB * 4)            // 36864
#define SMEM_TOTAL (SM_B0 + 2 * B_STAGE)   // 141312

__global__ __launch_bounds__(256, 1) void tc_gemm_exp_kernel(
    const float* __restrict__ q, const float* __restrict__ k,
    const float* __restrict__ logt, float* __restrict__ out)
{
    extern __shared__ char smem[];
    uint32_t sbase = smem_to_u32(smem);

    int bh = blockIdx.z;
    int bm = blockIdx.y;          // 16 tiles of 128 q-rows
    int bnq = blockIdx.x;         // 2 groups of 4 n-tiles (256 k-rows each)
    int tid = threadIdx.x;
    int warp = tid >> 5, lane = tid & 31;
    int wm = warp >> 2, wn = warp & 3;   // 2 x 4 warp grid
    int wmo = wm * 64, wno = wn * 64;    // warp tile 64 x 64

    const float* qb = q + ((size_t)bh * SEQ + (size_t)bm * 128) * DIM;
    const float* kg = k + ((size_t)bh * SEQ + (size_t)bnq * 1024) * DIM;

    // ---- B chunk issuer: tile tt (0..3), k-chunk cc (0..3), stage s ----
    auto issue_b = [&](int tt, int cc, int s) {
        uint32_t dst0 = sbase + SM_B0 + (uint32_t)(s * B_STAGE);
        const float* src0 = kg + (size_t)tt * 256 * DIM + cc * 32;
#pragma unroll
        for (int i = 0; i < 8; i++) {
            int id = tid + i * 256;          // float4 idx 0..2047
            int r = id >> 3, c4 = id & 7;
            CP_ASYNC16(dst0 + (uint32_t)((r * LDB + c4 * 4) * 4),
                       src0 + (size_t)r * DIM + c4 * 4);
        }
        CP_COMMIT();
    };

    // ---- prologue: A (full K) + B chunk 0 in group 0; B chunk 1 in group 1
#pragma unroll
    for (int i = 0; i < 16; i++) {
        int id = tid + i * 256;              // float4 idx 0..4095
        int r = id >> 5, c4 = id & 31;
        CP_ASYNC16(sbase + (uint32_t)((r * LDA + c4 * 4) * 4),
                   qb + (size_t)r * DIM + c4 * 4);
    }
    issue_b(0, 0, 0);     // commits group containing A + B(0,0)
    issue_b(0, 1, 1);

    // ---- fragment offsets ----
    int g = lane >> 3, lr = lane & 7;
    uint32_t aA[4], bOff[4];
#pragma unroll
    for (int mi = 0; mi < 4; mi++)
        aA[mi] = sbase +
            (uint32_t)(((wmo + mi * 16 + (g & 1) * 8 + lr) * LDA + (g >> 1) * 4) * 4);
#pragma unroll
    for (int p = 0; p < 4; p++)
        bOff[p] = (uint32_t)(((wno + p * 16 + (g >> 1) * 8 + lr) * LDB + (g & 1) * 4) * 4);

    // ---- hoisted scalars ----
    const float LOG2E = 1.442695040888963f;
    float lt = *logt;
    float temp = fminf(fmaxf(__expf(lt), 0.05f), 100.0f);
    float scl = LOG2E / temp;

    int gid = lane >> 2, tig = lane & 3;
    float rqv[4][2];
    {
        const float* rqp = g_rq + (size_t)bh * SEQ + (size_t)bm * 128;
#pragma unroll
        for (int mi = 0; mi < 4; mi++) {
            int r0 = wmo + mi * 16 + gid;
            rqv[mi][0] = rqp[r0];
            rqv[mi][1] = rqp[r0 + 8];
        }
    }

    float acc[4][8][4];

    // ---- main loop: 4 bn tiles x 4 K-chunks ----
    for (int t = 0; t < 4; t++) {
#pragma unroll
        for (int mi = 0; mi < 4; mi++)
#pragma unroll
            for (int ni = 0; ni < 8; ni++)
#pragma unroll
                for (int r = 0; r < 4; r++) acc[mi][ni][r] = 0.0f;

#pragma unroll
        for (int cc = 0; cc < 4; cc++) {
            int idx = t * 4 + cc;
            if (idx == 15) { CP_WAIT(0); } else { CP_WAIT(1); }
            __syncthreads();

            uint32_t stB = sbase + SM_B0 + (uint32_t)((idx & 1) * B_STAGE);
            uint32_t aCk = (uint32_t)(cc * 32 * 4);

#pragma unroll
            for (int s = 0; s < 4; s++) {
                uint32_t akb = aCk + (uint32_t)(s * 32);
                uint32_t bkb = (uint32_t)(s * 32);
                unsigned af[4][4], bf[4][4];
#pragma unroll
                for (int mi = 0; mi < 4; mi++) ldsm_x4(af[mi], aA[mi] + akb);
#pragma unroll
                for (int p = 0; p < 4; p++) ldsm_x4(bf[p], stB + bOff[p] + bkb);
#pragma unroll
                for (int mi = 0; mi < 4; mi++)
#pragma unroll
                    for (int p = 0; p < 4; p++) {
                        mma_tf32(acc[mi][2 * p],     af[mi], bf[p][0], bf[p][1]);
                        mma_tf32(acc[mi][2 * p + 1], af[mi], bf[p][2], bf[p][3]);
                    }
            }

            __syncthreads();   // everyone done reading this stage
            if (idx + 2 < 16) issue_b((idx + 2) >> 2, (idx + 2) & 3, idx & 1);
        }

        // ---- epilogue for tile t (next tile's B chunks already in flight) ----
        int n0 = bnq * 1024 + t * 256;
        const float* rkp = g_rk + (size_t)bh * SEQ + n0;
        float rkv[8][2];
#pragma unroll
        for (int ni = 0; ni < 8; ni++) {
            int c0 = wno + ni * 8 + tig * 2;
            float2 v = *reinterpret_cast<const float2*>(rkp + c0);
            rkv[ni][0] = v.x * scl;
            rkv[ni][1] = v.y * scl;
        }

#pragma unroll
        for (int mi = 0; mi < 4; mi++) {
            int r0 = wmo + mi * 16 + gid;
            float rq0 = rqv[mi][0], rq1 = rqv[mi][1];
            float* o0p = out + ((size_t)bh * SEQ + (size_t)(bm * 128 + r0)) * SEQ + n0;
            float* o1p = o0p + (size_t)8 * SEQ;
#pragma unroll
            for (int ni = 0; ni < 8; ni++) {
                int c0 = wno + ni * 8 + tig * 2;
                float2 o0, o1;
                o0.x = ex2f(acc[mi][ni][0] * rq0 * rkv[ni][0]) + 1e-6f;
                o0.y = ex2f(acc[mi][ni][1] * rq0 * rkv[ni][1]) + 1e-6f;
                o1.x = ex2f(acc[mi][ni][2] * rq1 * rkv[ni][0]) + 1e-6f;
                o1.y = ex2f(acc[mi][ni][3] * rq1 * rkv[ni][1]) + 1e-6f;
                *reinterpret_cast<float2*>(o0p + c0) = o0;
                *reinterpret_cast<float2*>(o1p + c0) = o1;
            }
        }
    }
}

// ---------------------------------------------------------------------------
// Launcher (graph-capturable: kernel launches only)
// ---------------------------------------------------------------------------
extern "C" void kernel_launch(void* const* d_in, const int* in_sizes, int n_in,
                              void* d_out, int out_size) {
    const float* q  = (const float*)d_in[0];
    const float* k  = (const float*)d_in[1];
    const float* lt = (const float*)d_in[2];
    float* out = (float*)d_out;

    norm_kernel<<<(2 * NROWS) / 8, 256>>>(q, k);

    cudaFuncSetAttribute(tc_gemm_exp_kernel,
                         cudaFuncAttributeMaxDynamicSharedMemorySize, SMEM_TOTAL);
    dim3 grid(2, 16, 32);  // (bn-quartet, bm, bh)
    tc_gemm_exp_kernel<<<grid, 256, SMEM_TOTAL>>>(q, k, lt, out);
}